// round 2
// baseline (speedup 1.0000x reference)
#include <cuda_runtime.h>
#include <math.h>

#define B_ 2
#define S_ 2048
#define D_ 1024
#define H_ 16
#define DK_ 64
#define NROWS (B_*S_)      // 4096
#define NBH (B_*H_)        // 32

// Scratch (allocation-free): module-load static device memory
__device__ float g_Q[NBH*S_*DK_];   // [b,h,s,dk]
__device__ float g_K[NBH*S_*DK_];
__device__ float g_V[NBH*S_*DK_];
__device__ float g_ctx[NROWS*D_];   // merged-head context
__device__ float g_rmax[NBH*S_];
__device__ float g_rinv[NBH*S_];

// GEMM tiling: 128x64 block tile, BK=16, 256 threads, 8x4 per thread
#define BM 128
#define BN 64
#define BK 16
#define LDA_P 132   // padded smem stride for A (transposed [k][m])
#define LDB_P 68    // padded smem stride for B ([k][n])

// ---------------------------------------------------------------------------
// Kernel 1: QKV projections.  Out = X @ W^T + b, stored split-head [b,h,s,dk]
// blockIdx.z selects which of Q/K/V.
// ---------------------------------------------------------------------------
__global__ void __launch_bounds__(256) proj_kernel(
    const float* __restrict__ Xq, const float* __restrict__ Xk, const float* __restrict__ Xv,
    const float* __restrict__ Wq, const float* __restrict__ bq,
    const float* __restrict__ Wk, const float* __restrict__ bk,
    const float* __restrict__ Wv, const float* __restrict__ bv)
{
    const int which = blockIdx.z;
    const float* X    = (which == 0) ? Xq : (which == 1) ? Xk : Xv;
    const float* W    = (which == 0) ? Wq : (which == 1) ? Wk : Wv;
    const float* bias = (which == 0) ? bq : (which == 1) ? bk : bv;
    float* Out        = (which == 0) ? g_Q : (which == 1) ? g_K : g_V;

    __shared__ __align__(16) float As[BK][LDA_P];
    __shared__ __align__(16) float Bs[BK][LDB_P];

    const int tid  = threadIdx.x;
    const int row0 = blockIdx.y * BM;   // row in [0, NROWS)
    const int col0 = blockIdx.x * BN;   // output feature j in [0, D)
    const int ty = tid >> 4, tx = tid & 15;

    float acc[8][4] = {};

    for (int kb = 0; kb < D_; kb += BK) {
        // A tile: 128 rows x 16 k  (2 float4 per thread), transpose into As[k][m]
        #pragma unroll
        for (int l = 0; l < 2; l++) {
            int i = tid + (l << 8);
            int ar = i >> 2, ac4 = i & 3;
            float4 v = *reinterpret_cast<const float4*>(&X[(size_t)(row0 + ar) * D_ + kb + ac4 * 4]);
            As[ac4*4+0][ar] = v.x; As[ac4*4+1][ar] = v.y;
            As[ac4*4+2][ar] = v.z; As[ac4*4+3][ar] = v.w;
        }
        // B tile: 64 j-rows x 16 k (W is [j][d], K-major), transpose into Bs[k][n]
        {
            int br = tid >> 2, bc4 = tid & 3;
            float4 v = *reinterpret_cast<const float4*>(&W[(size_t)(col0 + br) * D_ + kb + bc4 * 4]);
            Bs[bc4*4+0][br] = v.x; Bs[bc4*4+1][br] = v.y;
            Bs[bc4*4+2][br] = v.z; Bs[bc4*4+3][br] = v.w;
        }
        __syncthreads();
        #pragma unroll
        for (int k = 0; k < BK; ++k) {
            float a[8], bf[4];
            *reinterpret_cast<float4*>(&a[0]) = *reinterpret_cast<const float4*>(&As[k][ty*8]);
            *reinterpret_cast<float4*>(&a[4]) = *reinterpret_cast<const float4*>(&As[k][ty*8+4]);
            *reinterpret_cast<float4*>(&bf[0]) = *reinterpret_cast<const float4*>(&Bs[k][tx*4]);
            #pragma unroll
            for (int i = 0; i < 8; i++)
                #pragma unroll
                for (int j = 0; j < 4; j++)
                    acc[i][j] = fmaf(a[i], bf[j], acc[i][j]);
        }
        __syncthreads();
    }

    // Epilogue: add bias, store split-head  Out[((b*H+h)*S + s)*DK + dk]
    #pragma unroll
    for (int i = 0; i < 8; i++) {
        int m = row0 + ty * 8 + i;
        int b = m >> 11, s = m & (S_ - 1);
        #pragma unroll
        for (int j = 0; j < 4; j++) {
            int n = col0 + tx * 4 + j;
            int h = n >> 6, dk = n & (DK_ - 1);
            Out[(((size_t)(b * H_ + h)) * S_ + s) * DK_ + dk] = acc[i][j] + bias[n];
        }
    }
}

// ---------------------------------------------------------------------------
// Kernel 2: raw scores = Q @ K^T * 1/sqrt(DK), written to d_out weights region
// ---------------------------------------------------------------------------
__global__ void __launch_bounds__(256) scores_kernel(float* __restrict__ attn)
{
    const int bh   = blockIdx.z;
    const int row0 = blockIdx.y * BM;   // q
    const int col0 = blockIdx.x * BN;   // k
    const float* Qm = g_Q + (size_t)bh * S_ * DK_;
    const float* Km = g_K + (size_t)bh * S_ * DK_;

    __shared__ __align__(16) float As[BK][LDA_P];
    __shared__ __align__(16) float Bs[BK][LDB_P];

    const int tid = threadIdx.x;
    const int ty = tid >> 4, tx = tid & 15;
    float acc[8][4] = {};

    for (int kb = 0; kb < DK_; kb += BK) {
        #pragma unroll
        for (int l = 0; l < 2; l++) {
            int i = tid + (l << 8);
            int ar = i >> 2, ac4 = i & 3;
            float4 v = *reinterpret_cast<const float4*>(&Qm[(size_t)(row0 + ar) * DK_ + kb + ac4 * 4]);
            As[ac4*4+0][ar] = v.x; As[ac4*4+1][ar] = v.y;
            As[ac4*4+2][ar] = v.z; As[ac4*4+3][ar] = v.w;
        }
        {
            int br = tid >> 2, bc4 = tid & 3;
            float4 v = *reinterpret_cast<const float4*>(&Km[(size_t)(col0 + br) * DK_ + kb + bc4 * 4]);
            Bs[bc4*4+0][br] = v.x; Bs[bc4*4+1][br] = v.y;
            Bs[bc4*4+2][br] = v.z; Bs[bc4*4+3][br] = v.w;
        }
        __syncthreads();
        #pragma unroll
        for (int k = 0; k < BK; ++k) {
            float a[8], bf[4];
            *reinterpret_cast<float4*>(&a[0]) = *reinterpret_cast<const float4*>(&As[k][ty*8]);
            *reinterpret_cast<float4*>(&a[4]) = *reinterpret_cast<const float4*>(&As[k][ty*8+4]);
            *reinterpret_cast<float4*>(&bf[0]) = *reinterpret_cast<const float4*>(&Bs[k][tx*4]);
            #pragma unroll
            for (int i = 0; i < 8; i++)
                #pragma unroll
                for (int j = 0; j < 4; j++)
                    acc[i][j] = fmaf(a[i], bf[j], acc[i][j]);
        }
        __syncthreads();
    }

    const float scale = 0.125f;  // 1/sqrt(64)
    #pragma unroll
    for (int i = 0; i < 8; i++) {
        int q = row0 + ty * 8 + i;
        float4 o;
        o.x = acc[i][0] * scale; o.y = acc[i][1] * scale;
        o.z = acc[i][2] * scale; o.w = acc[i][3] * scale;
        *reinterpret_cast<float4*>(&attn[((size_t)bh * S_ + q) * S_ + col0 + tx * 4]) = o;
    }
}

// ---------------------------------------------------------------------------
// Kernel 3: per-row max and 1/sum(exp) over the raw scores
// ---------------------------------------------------------------------------
__global__ void __launch_bounds__(256) rowstat_kernel(const float* __restrict__ attn)
{
    const int row = blockIdx.x;                 // [0, NBH*S)
    const float* p = attn + (size_t)row * S_;
    const int tid = threadIdx.x;

    float v[8];
    float mx = -1e30f;
    #pragma unroll
    for (int i = 0; i < 8; i++) { v[i] = p[tid + (i << 8)]; mx = fmaxf(mx, v[i]); }

    __shared__ float red[8];
    #pragma unroll
    for (int o = 16; o > 0; o >>= 1) mx = fmaxf(mx, __shfl_xor_sync(0xffffffffu, mx, o));
    int warp = tid >> 5, lane = tid & 31;
    if (lane == 0) red[warp] = mx;
    __syncthreads();
    if (tid < 8) {
        float m = red[tid];
        #pragma unroll
        for (int o = 4; o > 0; o >>= 1) m = fmaxf(m, __shfl_xor_sync(0xffu, m, o));
        if (tid == 0) red[0] = m;
    }
    __syncthreads();
    mx = red[0];
    __syncthreads();

    float sum = 0.f;
    #pragma unroll
    for (int i = 0; i < 8; i++) sum += __expf(v[i] - mx);
    #pragma unroll
    for (int o = 16; o > 0; o >>= 1) sum += __shfl_xor_sync(0xffffffffu, sum, o);
    if (lane == 0) red[warp] = sum;
    __syncthreads();
    if (tid == 0) {
        float s = 0.f;
        #pragma unroll
        for (int w = 0; w < 8; w++) s += red[w];
        g_rmax[row] = mx;
        g_rinv[row] = 1.0f / s;
    }
}

// ---------------------------------------------------------------------------
// Kernel 4: normalize weights in place (write softmax to d_out) AND ctx = W @ V
// Block tile: 128 q-rows x full DK=64, so each weight element is touched once.
// ---------------------------------------------------------------------------
__global__ void __launch_bounds__(256) av_kernel(float* __restrict__ attn)
{
    const int bh   = blockIdx.z;
    const int row0 = blockIdx.y * BM;
    const int tid  = threadIdx.x;
    const int ty = tid >> 4, tx = tid & 15;

    __shared__ __align__(16) float As[BK][LDA_P];
    __shared__ __align__(16) float Bs[BK][LDB_P];
    __shared__ float rmaxS[BM], rinvS[BM];

    if (tid < BM) {
        rmaxS[tid] = g_rmax[bh * S_ + row0 + tid];
        rinvS[tid] = g_rinv[bh * S_ + row0 + tid];
    }
    __syncthreads();

    float* Abase = attn + ((size_t)bh * S_ + row0) * S_;
    const float* Vbase = g_V + (size_t)bh * S_ * DK_;

    float acc[8][4] = {};

    for (int kb = 0; kb < S_; kb += BK) {
        #pragma unroll
        for (int l = 0; l < 2; l++) {
            int i = tid + (l << 8);
            int ar = i >> 2, ac4 = i & 3;
            float4* gp = reinterpret_cast<float4*>(&Abase[(size_t)ar * S_ + kb + ac4 * 4]);
            float4 v = *gp;
            float m = rmaxS[ar], inv = rinvS[ar];
            v.x = __expf(v.x - m) * inv;
            v.y = __expf(v.y - m) * inv;
            v.z = __expf(v.z - m) * inv;
            v.w = __expf(v.w - m) * inv;
            *gp = v;  // normalized softmax weight -> final output
            As[ac4*4+0][ar] = v.x; As[ac4*4+1][ar] = v.y;
            As[ac4*4+2][ar] = v.z; As[ac4*4+3][ar] = v.w;
        }
        {
            int kr = tid >> 4, c4 = tid & 15;   // 16 k-rows x 64 dk (V is [s][dk])
            float4 v = *reinterpret_cast<const float4*>(&Vbase[(size_t)(kb + kr) * DK_ + c4 * 4]);
            *reinterpret_cast<float4*>(&Bs[kr][c4 * 4]) = v;
        }
        __syncthreads();
        #pragma unroll
        for (int k = 0; k < BK; ++k) {
            float a[8], bf[4];
            *reinterpret_cast<float4*>(&a[0]) = *reinterpret_cast<const float4*>(&As[k][ty*8]);
            *reinterpret_cast<float4*>(&a[4]) = *reinterpret_cast<const float4*>(&As[k][ty*8+4]);
            *reinterpret_cast<float4*>(&bf[0]) = *reinterpret_cast<const float4*>(&Bs[k][tx*4]);
            #pragma unroll
            for (int i = 0; i < 8; i++)
                #pragma unroll
                for (int j = 0; j < 4; j++)
                    acc[i][j] = fmaf(a[i], bf[j], acc[i][j]);
        }
        __syncthreads();
    }

    // Epilogue: merged-head context  g_ctx[(b*S+q)*D + h*DK + dk]
    const int b = bh >> 4, h = bh & (H_ - 1);
    #pragma unroll
    for (int i = 0; i < 8; i++) {
        int q = row0 + ty * 8 + i;
        float4 o;
        o.x = acc[i][0]; o.y = acc[i][1]; o.z = acc[i][2]; o.w = acc[i][3];
        *reinterpret_cast<float4*>(&g_ctx[((size_t)(b * S_ + q)) * D_ + h * DK_ + tx * 4]) = o;
    }
}

// ---------------------------------------------------------------------------
// Kernel 5: output projection  out = ctx @ W_o^T + b_o
// ---------------------------------------------------------------------------
__global__ void __launch_bounds__(256) outproj_kernel(
    const float* __restrict__ Wo, const float* __restrict__ bo, float* __restrict__ out)
{
    __shared__ __align__(16) float As[BK][LDA_P];
    __shared__ __align__(16) float Bs[BK][LDB_P];

    const int tid  = threadIdx.x;
    const int row0 = blockIdx.y * BM;
    const int col0 = blockIdx.x * BN;
    const int ty = tid >> 4, tx = tid & 15;
    float acc[8][4] = {};

    for (int kb = 0; kb < D_; kb += BK) {
        #pragma unroll
        for (int l = 0; l < 2; l++) {
            int i = tid + (l << 8);
            int ar = i >> 2, ac4 = i & 3;
            float4 v = *reinterpret_cast<const float4*>(&g_ctx[(size_t)(row0 + ar) * D_ + kb + ac4 * 4]);
            As[ac4*4+0][ar] = v.x; As[ac4*4+1][ar] = v.y;
            As[ac4*4+2][ar] = v.z; As[ac4*4+3][ar] = v.w;
        }
        {
            int br = tid >> 2, bc4 = tid & 3;
            float4 v = *reinterpret_cast<const float4*>(&Wo[(size_t)(col0 + br) * D_ + kb + bc4 * 4]);
            Bs[bc4*4+0][br] = v.x; Bs[bc4*4+1][br] = v.y;
            Bs[bc4*4+2][br] = v.z; Bs[bc4*4+3][br] = v.w;
        }
        __syncthreads();
        #pragma unroll
        for (int k = 0; k < BK; ++k) {
            float a[8], bf[4];
            *reinterpret_cast<float4*>(&a[0]) = *reinterpret_cast<const float4*>(&As[k][ty*8]);
            *reinterpret_cast<float4*>(&a[4]) = *reinterpret_cast<const float4*>(&As[k][ty*8+4]);
            *reinterpret_cast<float4*>(&bf[0]) = *reinterpret_cast<const float4*>(&Bs[k][tx*4]);
            #pragma unroll
            for (int i = 0; i < 8; i++)
                #pragma unroll
                for (int j = 0; j < 4; j++)
                    acc[i][j] = fmaf(a[i], bf[j], acc[i][j]);
        }
        __syncthreads();
    }

    #pragma unroll
    for (int i = 0; i < 8; i++) {
        int m = row0 + ty * 8 + i;
        int n = col0 + tx * 4;
        float4 o;
        o.x = acc[i][0] + bo[n + 0];
        o.y = acc[i][1] + bo[n + 1];
        o.z = acc[i][2] + bo[n + 2];
        o.w = acc[i][3] + bo[n + 3];
        *reinterpret_cast<float4*>(&out[(size_t)m * D_ + n]) = o;
    }
}

// ---------------------------------------------------------------------------
extern "C" void kernel_launch(void* const* d_in, const int* in_sizes, int n_in,
                              void* d_out, int out_size)
{
    const float* query = (const float*)d_in[0];
    const float* key_  = (const float*)d_in[1];
    const float* value = (const float*)d_in[2];
    const float* W_q = (const float*)d_in[3];
    const float* b_q = (const float*)d_in[4];
    const float* W_k = (const float*)d_in[5];
    const float* b_k = (const float*)d_in[6];
    const float* W_v = (const float*)d_in[7];
    const float* b_v = (const float*)d_in[8];
    const float* W_o = (const float*)d_in[9];
    const float* b_o = (const float*)d_in[10];

    float* out  = (float*)d_out;                       // [B,S,D]
    float* attn = out + (size_t)B_ * S_ * D_;          // [B,H,S,S]

    proj_kernel<<<dim3(D_/BN, NROWS/BM, 3), 256>>>(
        query, key_, value, W_q, b_q, W_k, b_k, W_v, b_v);

    scores_kernel<<<dim3(S_/BN, S_/BM, NBH), 256>>>(attn);

    rowstat_kernel<<<NBH * S_, 256>>>(attn);

    av_kernel<<<dim3(1, S_/BM, NBH), 256>>>(attn);

    outproj_kernel<<<dim3(D_/BN, NROWS/BM), 256>>>(W_o, b_o, out);
}